// round 7
// baseline (speedup 1.0000x reference)
#include <cuda_runtime.h>

// CRF loss forward, B=512, N=1024, K=64, sm_100a.
// TWO independent chains per warp (latency hiding via chain interleave).
// Lane owns states 2l, 2l+1 of each chain. Linear-domain scan, shared
// register-resident exp(trans), f32x2 FMAs, exp(emit) one step ahead,
// branchless body, R1-exact renorm per chain (warp-max every 4 steps).

typedef unsigned long long ull;
#define FULLMASK 0xffffffffu

__device__ __forceinline__ void fma2(ull &d, ull a, ull b) {
    asm("fma.rn.f32x2 %0, %1, %2, %0;" : "+l"(d) : "l"(a), "l"(b));
}
__device__ __forceinline__ ull pack2(float x, float y) {
    ull r; asm("mov.b64 %0, {%1, %2};" : "=l"(r) : "f"(x), "f"(y)); return r;
}
__device__ __forceinline__ void unpack2(ull v, float &x, float &y) {
    asm("mov.b64 {%0, %1}, %2;" : "=f"(x), "=f"(y) : "l"(v));
}
__device__ __forceinline__ float ex2f(float x) {
    float r; asm("ex2.approx.f32 %0, %1;" : "=f"(r) : "f"(x)); return r;
}
__device__ __forceinline__ float lg2f(float x) {
    float r; asm("lg2.approx.f32 %0, %1;" : "=f"(r) : "f"(x)); return r;
}

__global__ __launch_bounds__(32) void crf_fwd_kernel(
    const float* __restrict__ y_pred,   // [B, N, K]
    const float* __restrict__ trans,    // [K, K]
    const int*   __restrict__ y_true,   // [B, N]
    float*       __restrict__ out)      // [B]
{
    constexpr int N = 1024;
    constexpr int K = 64;
    constexpr float LOG2E = 1.4426950408889634f;

    const int lane = threadIdx.x;
    const int bA   = blockIdx.x * 2;
    const int bB   = bA + 1;
    const int j0   = 2 * lane, j1 = j0 + 1;

    __shared__ ull sh_a[2][2][32];   // [chain][buf][lane]

    // ---- E = exp(trans) columns j0, j1 in registers (shared by both chains) ----
    ull Er0[32], Er1[32];
    #pragma unroll
    for (int p = 0; p < 32; p++) {
        float t00 = __ldg(&trans[(2 * p)     * K + j0]);
        float t01 = __ldg(&trans[(2 * p + 1) * K + j0]);
        float t10 = __ldg(&trans[(2 * p)     * K + j1]);
        float t11 = __ldg(&trans[(2 * p + 1) * K + j1]);
        Er0[p] = pack2(ex2f(t00 * LOG2E), ex2f(t01 * LOG2E));
        Er1[p] = pack2(ex2f(t10 * LOG2E), ex2f(t11 * LOG2E));
    }

    const float2* emrowA = (const float2*)y_pred + (size_t)bA * N * 32;
    const float2* emrowB = (const float2*)y_pred + (size_t)bB * N * 32;
    const int*    ytrowA = y_true + (size_t)bA * N;
    const int*    ytrowB = y_true + (size_t)bB * N;

    // ---- per-chain persistent state ----
    float  ptA = 0.f, ptB = 0.f;
    double c2A, c2B;
    int    ytprevA, ytprevB;
    bool   pmA, pmB;
    float  s0pA, s1pA, s0pB, s1pB;

    // ---- t = 0 init (both chains) ----
    #define INIT0(S, emrow, ytrow, ci)                                         \
    {                                                                          \
        float2 v = emrow[lane];                                                \
        bool okl = (v.x > -1e6f) & (v.y > -1e6f);                              \
        bool ok0 = __all_sync(FULLMASK, okl);                                  \
        float mv0 = ok0 ? v.x : 0.f;                                           \
        float mv1 = ok0 ? v.y : 0.f;                                           \
        float mx = fmaxf(mv0, mv1);                                            \
        _Pragma("unroll")                                                      \
        for (int o = 16; o; o >>= 1)                                           \
            mx = fmaxf(mx, __shfl_xor_sync(FULLMASK, mx, o));                  \
        s0p##S = ex2f((mv0 - mx) * LOG2E);                                     \
        s1p##S = ex2f((mv1 - mx) * LOG2E);                                     \
        c2##S = (double)mx * 1.4426950408889634;                               \
        ytprev##S = ytrow[0];                                                  \
        if (ok0 && (ytprev##S >> 1) == lane)                                   \
            pt##S += (ytprev##S & 1) ? v.y : v.x;                              \
        pm##S = ok0;                                                           \
        sh_a[ci][0][lane] = pack2(s0p##S, s1p##S);                             \
    }
    INIT0(A, emrowA, ytrowA, 0)
    INIT0(B, emrowB, ytrowB, 1)
    #undef INIT0
    __syncwarp();

    // ---- prefetch rings (depth 4) + exp-ahead, both chains ----
    float2 remA[4], remB[4]; int rytA[4], rytB[4];
    #pragma unroll
    for (int k = 0; k < 4; k++) {
        remA[k] = __ldcs(&emrowA[(1 + k) * 32 + lane]);
        remB[k] = __ldcs(&emrowB[(1 + k) * 32 + lane]);
        rytA[k] = __ldg(&ytrowA[1 + k]);
        rytB[k] = __ldg(&ytrowB[1 + k]);
    }
    float2 enextA, enextB;
    enextA.x = ex2f(remA[0].x * LOG2E);
    enextA.y = ex2f(remA[0].y * LOG2E);
    enextB.x = ex2f(remB[0].x * LOG2E);
    enextB.y = ex2f(remB[0].y * LOG2E);

    int buf = 0;

    // one double-step: advances BOTH chains by one t; SLOT/RENORM compile-time
    #define STEP2(T, SLOT, RENORM)                                             \
    {                                                                          \
        const int t  = (T);                                                    \
        const int sl = (SLOT);                                                 \
        float emA0 = remA[sl].x, emA1 = remA[sl].y;                            \
        float emB0 = remB[sl].x, emB1 = remB[sl].y;                            \
        int   ytA  = rytA[sl],   ytB  = rytB[sl];                              \
        float2 ecurA = enextA, ecurB = enextB;                                 \
        float2 nxtA = remA[(sl + 1) & 3];                                      \
        float2 nxtB = remB[(sl + 1) & 3];                                      \
        enextA.x = ex2f(nxtA.x * LOG2E);                                       \
        enextA.y = ex2f(nxtA.y * LOG2E);                                       \
        enextB.x = ex2f(nxtB.x * LOG2E);                                       \
        enextB.y = ex2f(nxtB.y * LOG2E);                                       \
        int tf = t + 4; tf = (tf > N - 1) ? (N - 1) : tf;                      \
        remA[sl] = __ldcs(&emrowA[tf * 32 + lane]);                            \
        remB[sl] = __ldcs(&emrowB[tf * 32 + lane]);                            \
        rytA[sl] = __ldg(&ytrowA[tf]);                                         \
        rytB[sl] = __ldg(&ytrowB[tf]);                                         \
        bool okA = __all_sync(FULLMASK, (emA0 > -1e6f) & (emA1 > -1e6f));      \
        bool okB = __all_sync(FULLMASK, (emB0 > -1e6f) & (emB1 > -1e6f));      \
        const ulonglong2* apA = (const ulonglong2*)sh_a[0][buf];               \
        const ulonglong2* apB = (const ulonglong2*)sh_a[1][buf];               \
        ull A0 = 0ull, A1 = 0ull, B0 = 0ull, B1 = 0ull;                        \
        ull C0 = 0ull, C1 = 0ull, D0 = 0ull, D1 = 0ull;                        \
        _Pragma("unroll")                                                      \
        for (int q = 0; q < 8; q++) {                                          \
            ulonglong2 vA0 = apA[2 * q];                                       \
            ulonglong2 vA1 = apA[2 * q + 1];                                   \
            ulonglong2 vB0 = apB[2 * q];                                       \
            ulonglong2 vB1 = apB[2 * q + 1];                                   \
            fma2(A0, vA0.x, Er0[4 * q]);                                       \
            fma2(C0, vB0.x, Er0[4 * q]);                                       \
            fma2(B0, vA0.x, Er1[4 * q]);                                       \
            fma2(D0, vB0.x, Er1[4 * q]);                                       \
            fma2(A1, vA0.y, Er0[4 * q + 1]);                                   \
            fma2(C1, vB0.y, Er0[4 * q + 1]);                                   \
            fma2(B1, vA0.y, Er1[4 * q + 1]);                                   \
            fma2(D1, vB0.y, Er1[4 * q + 1]);                                   \
            fma2(A0, vA1.x, Er0[4 * q + 2]);                                   \
            fma2(C0, vB1.x, Er0[4 * q + 2]);                                   \
            fma2(B0, vA1.x, Er1[4 * q + 2]);                                   \
            fma2(D0, vB1.x, Er1[4 * q + 2]);                                   \
            fma2(A1, vA1.y, Er0[4 * q + 3]);                                   \
            fma2(C1, vB1.y, Er0[4 * q + 3]);                                   \
            fma2(B1, vA1.y, Er1[4 * q + 3]);                                   \
            fma2(D1, vB1.y, Er1[4 * q + 3]);                                   \
        }                                                                      \
        float xa, ya, xb, yb, xc, yc, xd, yd;                                  \
        unpack2(A0, xa, ya); unpack2(A1, xb, yb);                              \
        unpack2(B0, xc, yc); unpack2(B1, xd, yd);                              \
        float sA0 = ((xa + xb) + (ya + yb)) * ecurA.x;                         \
        float sA1 = ((xc + xd) + (yc + yd)) * ecurA.y;                         \
        unpack2(C0, xa, ya); unpack2(C1, xb, yb);                              \
        unpack2(D0, xc, yc); unpack2(D1, xd, yd);                              \
        float sB0 = ((xa + xb) + (ya + yb)) * ecurB.x;                         \
        float sB1 = ((xc + xd) + (yc + yd)) * ecurB.y;                         \
        sA0 = okA ? sA0 : s0pA;  sA1 = okA ? sA1 : s1pA;                       \
        sB0 = okB ? sB0 : s0pB;  sB1 = okB ? sB1 : s1pB;                       \
        if (okA && (ytA >> 1) == lane) {                                       \
            ptA += (ytA & 1) ? emA1 : emA0;                                    \
            if (pmA) ptA += __ldg(&trans[ytprevA * K + ytA]);                  \
        }                                                                      \
        if (okB && (ytB >> 1) == lane) {                                       \
            ptB += (ytB & 1) ? emB1 : emB0;                                    \
            if (pmB) ptB += __ldg(&trans[ytprevB * K + ytB]);                  \
        }                                                                      \
        pmA = okA; ytprevA = ytA;                                              \
        pmB = okB; ytprevB = ytB;                                              \
        if (RENORM) {                                                          \
            float rA = fmaxf(sA0, sA1);                                        \
            float rB = fmaxf(sB0, sB1);                                        \
            _Pragma("unroll")                                                  \
            for (int o = 16; o; o >>= 1) {                                     \
                rA = fmaxf(rA, __shfl_xor_sync(FULLMASK, rA, o));              \
                rB = fmaxf(rB, __shfl_xor_sync(FULLMASK, rB, o));              \
            }                                                                  \
            float invA = 1.0f / rA;                                            \
            float invB = 1.0f / rB;                                            \
            sA0 *= invA; sA1 *= invA;                                          \
            sB0 *= invB; sB1 *= invB;                                          \
            c2A += (double)lg2f(rA);                                           \
            c2B += (double)lg2f(rB);                                           \
        }                                                                      \
        s0pA = sA0; s1pA = sA1;                                                \
        s0pB = sB0; s1pB = sB1;                                                \
        sh_a[0][buf ^ 1][lane] = pack2(sA0, sA1);                              \
        sh_a[1][buf ^ 1][lane] = pack2(sB0, sB1);                              \
        buf ^= 1;                                                              \
        __syncwarp();                                                          \
    }

    // 255 groups of 4 (t = 1 .. 1020), renorm on last step of each group
    for (int g = 0; g < 255; g++) {
        const int tb = 1 + 4 * g;
        STEP2(tb + 0, 0, false)
        STEP2(tb + 1, 1, false)
        STEP2(tb + 2, 2, false)
        STEP2(tb + 3, 3, true)
    }
    // tail: t = 1021, 1022, 1023 (constant slots, no renorm)
    STEP2(1021, 0, false)
    STEP2(1022, 1, false)
    STEP2(1023, 2, false)
    #undef STEP2

    // ---- finalize both chains: log_norm - target_score ----
    float ssumA = s0pA + s1pA;
    float ssumB = s0pB + s1pB;
    #pragma unroll
    for (int o = 16; o; o >>= 1) {
        ssumA += __shfl_xor_sync(FULLMASK, ssumA, o);
        ssumB += __shfl_xor_sync(FULLMASK, ssumB, o);
        ptA   += __shfl_xor_sync(FULLMASK, ptA,   o);
        ptB   += __shfl_xor_sync(FULLMASK, ptB,   o);
    }
    if (lane == 0) {
        double lognormA = (c2A + (double)lg2f(ssumA)) * 0.6931471805599453;
        double lognormB = (c2B + (double)lg2f(ssumB)) * 0.6931471805599453;
        out[bA] = (float)(lognormA - (double)ptA);
        out[bB] = (float)(lognormB - (double)ptB);
    }
}

extern "C" void kernel_launch(void* const* d_in, const int* in_sizes, int n_in,
                              void* d_out, int out_size) {
    const float* y_pred = (const float*)d_in[0];
    const float* trans  = (const float*)d_in[1];
    const int*   y_true = (const int*)d_in[2];
    float* out = (float*)d_out;

    const int B = in_sizes[2] / 1024;   // 512
    crf_fwd_kernel<<<B / 2, 32>>>(y_pred, trans, y_true, out);
}

// round 8
// speedup vs baseline: 1.7942x; 1.7942x over previous
#include <cuda_runtime.h>
#include <cstdint>

// CRF loss forward, B=512, N=1024, K=64, sm_100a.
// One warp per chain. Linear-domain scan, register-resident exp(trans),
// f32x2 FMAs. Emits streamed via cp.async into a 4x8-step SMEM ring
// (compiler-proof prefetch, 2-group lead); y_true staged to SMEM once.
// R1-exact renorm every 4 steps (warp-max, divide, double c2 += lg2f).

typedef unsigned long long ull;
#define FULLMASK 0xffffffffu

__device__ __forceinline__ void fma2(ull &d, ull a, ull b) {
    asm("fma.rn.f32x2 %0, %1, %2, %0;" : "+l"(d) : "l"(a), "l"(b));
}
__device__ __forceinline__ ull pack2(float x, float y) {
    ull r; asm("mov.b64 %0, {%1, %2};" : "=l"(r) : "f"(x), "f"(y)); return r;
}
__device__ __forceinline__ void unpack2(ull v, float &x, float &y) {
    asm("mov.b64 {%0, %1}, %2;" : "=f"(x), "=f"(y) : "l"(v));
}
__device__ __forceinline__ float ex2f(float x) {
    float r; asm("ex2.approx.f32 %0, %1;" : "=f"(r) : "f"(x)); return r;
}
__device__ __forceinline__ float lg2f(float x) {
    float r; asm("lg2.approx.f32 %0, %1;" : "=f"(r) : "f"(x)); return r;
}
__device__ __forceinline__ uint32_t s2u(const void* p) {
    uint32_t a;
    asm("{ .reg .u64 t; cvta.to.shared.u64 t, %1; cvt.u32.u64 %0, t; }"
        : "=r"(a) : "l"(p));
    return a;
}
__device__ __forceinline__ void cp16(uint32_t dst, const void* src) {
    asm volatile("cp.async.cg.shared.global [%0], [%1], 16;"
                 :: "r"(dst), "l"(src));
}
#define CP_COMMIT() asm volatile("cp.async.commit_group;")

__global__ __launch_bounds__(32) void crf_fwd_kernel(
    const float* __restrict__ y_pred,   // [B, N, K]
    const float* __restrict__ trans,    // [K, K]
    const int*   __restrict__ y_true,   // [B, N]
    float*       __restrict__ out)      // [B]
{
    constexpr int N = 1024;
    constexpr int K = 64;
    constexpr float LOG2E = 1.4426950408889634f;

    const int b    = blockIdx.x;
    const int lane = threadIdx.x;
    const int j0   = 2 * lane, j1 = j0 + 1;

    __shared__ __align__(16) float sh_em[4 * 8 * 64];  // 4-buffer x 8-step emit ring
    __shared__ __align__(16) int   sh_yt[N];           // full y_true row
    __shared__ ull sh_a[2][32];                        // double-buffered alpha

    const float* emrow_f = y_pred + (size_t)b * N * K;
    const int*   ytrow   = y_true + (size_t)b * N;
    const uint32_t em_u32 = s2u(sh_em);

    // issue one 8-step (2KB) emit group into ring buffer (GP&3)
    #define PREFETCH(GP)                                                       \
    {                                                                          \
        int bt = (GP) * 8; if (bt > N - 8) bt = N - 8;                         \
        const char* src = (const char*)(emrow_f + (size_t)bt * K) + lane * 16; \
        uint32_t dst = em_u32 + (uint32_t)(((GP) & 3) * 2048) + lane * 16;     \
        cp16(dst,        src);                                                 \
        cp16(dst +  512, src +  512);                                          \
        cp16(dst + 1024, src + 1024);                                          \
        cp16(dst + 1536, src + 1536);                                          \
        CP_COMMIT();                                                           \
    }

    PREFETCH(0)
    PREFETCH(1)

    // ---- stage y_true row (4KB) into shared ----
    {
        const int4* ytg = (const int4*)ytrow;
        int4* yts = (int4*)sh_yt;
        #pragma unroll
        for (int i = 0; i < 8; i++) yts[lane + 32 * i] = ytg[lane + 32 * i];
    }

    // ---- E = exp(trans) columns j0, j1 in registers (overlaps cp.async) ----
    ull Er0[32], Er1[32];
    #pragma unroll
    for (int p = 0; p < 32; p++) {
        float t00 = __ldg(&trans[(2 * p)     * K + j0]);
        float t01 = __ldg(&trans[(2 * p + 1) * K + j0]);
        float t10 = __ldg(&trans[(2 * p)     * K + j1]);
        float t11 = __ldg(&trans[(2 * p + 1) * K + j1]);
        Er0[p] = pack2(ex2f(t00 * LOG2E), ex2f(t01 * LOG2E));
        Er1[p] = pack2(ex2f(t10 * LOG2E), ex2f(t11 * LOG2E));
    }

    asm volatile("cp.async.wait_group 1;");   // group 0 (steps 0..7) complete
    __syncwarp();

    // ---- t = 0 init (from ring slot 0) ----
    float  pt = 0.f;
    double c2;
    int    ytprev;
    bool   pm;
    float  s0p, s1p;
    {
        float2 v = *(const float2*)(sh_em + 2 * lane);
        bool okl = (v.x > -1e6f) & (v.y > -1e6f);
        bool ok0 = __all_sync(FULLMASK, okl);
        float mv0 = ok0 ? v.x : 0.f;
        float mv1 = ok0 ? v.y : 0.f;
        float mx = fmaxf(mv0, mv1);
        #pragma unroll
        for (int o = 16; o; o >>= 1) mx = fmaxf(mx, __shfl_xor_sync(FULLMASK, mx, o));
        s0p = ex2f((mv0 - mx) * LOG2E);
        s1p = ex2f((mv1 - mx) * LOG2E);
        c2 = (double)mx * 1.4426950408889634;
        ytprev = sh_yt[0];
        if (ok0 && (ytprev >> 1) == lane) pt += (ytprev & 1) ? v.y : v.x;
        pm = ok0;
        sh_a[0][lane] = pack2(s0p, s1p);
    }
    __syncwarp();

    int buf = 0;

    // one scan step; KK = slot within group buffer (compile-time), RENORM compile-time
    #define STEP(TT, KK, RENORM)                                               \
    {                                                                          \
        float2 em = *(const float2*)(ebase + (KK) * 64 + 2 * lane);            \
        float e0 = ex2f(em.x * LOG2E);                                         \
        float e1 = ex2f(em.y * LOG2E);                                         \
        bool ok = __all_sync(FULLMASK, (em.x > -1e6f) & (em.y > -1e6f));       \
        int yt = sh_yt[(TT)];                                                  \
        const ulonglong2* ap = (const ulonglong2*)sh_a[buf];                   \
        ull A0 = 0ull, A1 = 0ull, B0 = 0ull, B1 = 0ull;                        \
        _Pragma("unroll")                                                      \
        for (int q = 0; q < 8; q++) {                                          \
            ulonglong2 v0 = ap[2 * q];                                         \
            ulonglong2 v1 = ap[2 * q + 1];                                     \
            fma2(A0, v0.x, Er0[4 * q]);                                        \
            fma2(B0, v0.x, Er1[4 * q]);                                        \
            fma2(A1, v0.y, Er0[4 * q + 1]);                                    \
            fma2(B1, v0.y, Er1[4 * q + 1]);                                    \
            fma2(A0, v1.x, Er0[4 * q + 2]);                                    \
            fma2(B0, v1.x, Er1[4 * q + 2]);                                    \
            fma2(A1, v1.y, Er0[4 * q + 3]);                                    \
            fma2(B1, v1.y, Er1[4 * q + 3]);                                    \
        }                                                                      \
        float xa, ya, xb, yb, xc, yc, xd, yd;                                  \
        unpack2(A0, xa, ya); unpack2(A1, xb, yb);                              \
        unpack2(B0, xc, yc); unpack2(B1, xd, yd);                              \
        float s0n = ((xa + xb) + (ya + yb)) * e0;                              \
        float s1n = ((xc + xd) + (yc + yd)) * e1;                              \
        float s0 = ok ? s0n : s0p;                                             \
        float s1 = ok ? s1n : s1p;                                             \
        if (ok && (yt >> 1) == lane) {                                         \
            pt += (yt & 1) ? em.y : em.x;                                      \
            if (pm) pt += __ldg(&trans[ytprev * K + yt]);                      \
        }                                                                      \
        pm = ok; ytprev = yt;                                                  \
        if (RENORM) {                                                          \
            float r = fmaxf(s0, s1);                                           \
            _Pragma("unroll")                                                  \
            for (int o = 16; o; o >>= 1)                                       \
                r = fmaxf(r, __shfl_xor_sync(FULLMASK, r, o));                 \
            float inv = 1.0f / r;                                              \
            s0 *= inv; s1 *= inv;                                              \
            c2 += (double)lg2f(r);                                             \
        }                                                                      \
        s0p = s0; s1p = s1;                                                    \
        sh_a[buf ^ 1][lane] = pack2(s0, s1);                                   \
        buf ^= 1;                                                              \
        __syncwarp();                                                          \
    }

    // ---- group 0: t = 1..7 (buffer 0 already resident) ----
    {
        PREFETCH(2)
        asm volatile("cp.async.wait_group 2;");
        __syncwarp();
        const float* ebase = sh_em;
        STEP(1, 1, false)
        STEP(2, 2, false)
        STEP(3, 3, false)
        STEP(4, 4, true)
        STEP(5, 5, false)
        STEP(6, 6, false)
        STEP(7, 7, false)
    }

    // ---- groups 1..127: t = 8..1023, renorm at t % 4 == 0 (k = 0, 4) ----
    for (int G = 1; G < 128; G++) {
        PREFETCH(G + 2)
        asm volatile("cp.async.wait_group 2;");
        __syncwarp();
        const float* ebase = sh_em + (G & 3) * 512;
        const int t0 = G * 8;
        STEP(t0 + 0, 0, true)
        STEP(t0 + 1, 1, false)
        STEP(t0 + 2, 2, false)
        STEP(t0 + 3, 3, false)
        STEP(t0 + 4, 4, true)
        STEP(t0 + 5, 5, false)
        STEP(t0 + 6, 6, false)
        STEP(t0 + 7, 7, false)
    }
    #undef STEP
    #undef PREFETCH

    // ---- finalize: log_norm - target_score ----
    float ssum = s0p + s1p;
    #pragma unroll
    for (int o = 16; o; o >>= 1) {
        ssum += __shfl_xor_sync(FULLMASK, ssum, o);
        pt   += __shfl_xor_sync(FULLMASK, pt,   o);
    }
    if (lane == 0) {
        double lognorm = (c2 + (double)lg2f(ssum)) * 0.6931471805599453;
        out[b] = (float)(lognorm - (double)pt);
    }
}

extern "C" void kernel_launch(void* const* d_in, const int* in_sizes, int n_in,
                              void* d_out, int out_size) {
    const float* y_pred = (const float*)d_in[0];
    const float* trans  = (const float*)d_in[1];
    const int*   y_true = (const int*)d_in[2];
    float* out = (float*)d_out;

    const int B = in_sizes[2] / 1024;   // 512
    crf_fwd_kernel<<<B, 32>>>(y_pred, trans, y_true, out);
}

// round 10
// speedup vs baseline: 2.2542x; 1.2564x over previous
#include <cuda_runtime.h>
#include <cstdint>

// CRF loss forward, B=512, N=1024, K=64, sm_100a.
// 4 chains per 128-thread block (one warp per SMSP, no scheduler saturation).
// Per warp: linear-domain scan, register-resident exp(trans), f32x2 FMAs,
// cp.async emit streaming (4x8-step ring), branch-free score gather,
// LAZY renorm every 4 steps: warp-max butterfly after the sync, 1/r folded
// into the next step's emit scale (off the critical path), c2 double.

typedef unsigned long long ull;
#define FULLMASK 0xffffffffu

__device__ __forceinline__ void fma2(ull &d, ull a, ull b) {
    asm("fma.rn.f32x2 %0, %1, %2, %0;" : "+l"(d) : "l"(a), "l"(b));
}
__device__ __forceinline__ ull pack2(float x, float y) {
    ull r; asm("mov.b64 %0, {%1, %2};" : "=l"(r) : "f"(x), "f"(y)); return r;
}
__device__ __forceinline__ void unpack2(ull v, float &x, float &y) {
    asm("mov.b64 {%0, %1}, %2;" : "=f"(x), "=f"(y) : "l"(v));
}
__device__ __forceinline__ float ex2f(float x) {
    float r; asm("ex2.approx.f32 %0, %1;" : "=f"(r) : "f"(x)); return r;
}
__device__ __forceinline__ float lg2f(float x) {
    float r; asm("lg2.approx.f32 %0, %1;" : "=f"(r) : "f"(x)); return r;
}
__device__ __forceinline__ float warp_maxf(float x) {
    #pragma unroll
    for (int o = 16; o; o >>= 1) x = fmaxf(x, __shfl_xor_sync(FULLMASK, x, o));
    return x;
}
__device__ __forceinline__ uint32_t s2u(const void* p) {
    uint32_t a;
    asm("{ .reg .u64 t; cvta.to.shared.u64 t, %1; cvt.u32.u64 %0, t; }"
        : "=r"(a) : "l"(p));
    return a;
}
__device__ __forceinline__ void cp16(uint32_t dst, const void* src) {
    asm volatile("cp.async.cg.shared.global [%0], [%1], 16;"
                 :: "r"(dst), "l"(src));
}
#define CP_COMMIT() asm volatile("cp.async.commit_group;")

__global__ __launch_bounds__(128) void crf_fwd_kernel(
    const float* __restrict__ y_pred,   // [B, N, K]
    const float* __restrict__ trans,    // [K, K]
    const int*   __restrict__ y_true,   // [B, N]
    float*       __restrict__ out)      // [B]
{
    constexpr int N = 1024;
    constexpr int K = 64;
    constexpr float LOG2E = 1.4426950408889634f;

    const int tid  = threadIdx.x;
    const int w    = tid >> 5;          // warp -> SMSP w
    const int lane = tid & 31;
    const int b    = blockIdx.x * 4 + w;
    const int j0   = 2 * lane, j1 = j0 + 1;

    __shared__ __align__(16) float sh_em[4][4 * 512];  // per-warp 4-buf emit ring (8KB)
    __shared__ ull sh_a[4][2][32];                     // per-warp double-buffered alpha

    const float* emrow_f = y_pred + (size_t)b * N * K;
    const int*   ytrow   = y_true + (size_t)b * N;
    const uint32_t em_u32 = s2u(sh_em[w]);

    // issue one 8-step (2KB) emit group into ring buffer (GP&3)
    #define PREFETCH(GP)                                                       \
    {                                                                          \
        int bt = (GP) * 8; if (bt > N - 8) bt = N - 8;                         \
        const char* src = (const char*)(emrow_f + (size_t)bt * K) + lane * 16; \
        uint32_t dst = em_u32 + (uint32_t)(((GP) & 3) * 2048) + lane * 16;     \
        cp16(dst,        src);                                                 \
        cp16(dst +  512, src +  512);                                          \
        cp16(dst + 1024, src + 1024);                                          \
        cp16(dst + 1536, src + 1536);                                          \
        CP_COMMIT();                                                           \
    }

    PREFETCH(0)
    PREFETCH(1)

    // ---- E = exp(trans) columns j0, j1 in registers (overlaps cp.async) ----
    ull Er0[32], Er1[32];
    #pragma unroll
    for (int p = 0; p < 32; p++) {
        float t00 = __ldg(&trans[(2 * p)     * K + j0]);
        float t01 = __ldg(&trans[(2 * p + 1) * K + j0]);
        float t10 = __ldg(&trans[(2 * p)     * K + j1]);
        float t11 = __ldg(&trans[(2 * p + 1) * K + j1]);
        Er0[p] = pack2(ex2f(t00 * LOG2E), ex2f(t01 * LOG2E));
        Er1[p] = pack2(ex2f(t10 * LOG2E), ex2f(t11 * LOG2E));
    }

    asm volatile("cp.async.wait_group 1;");   // group 0 resident
    __syncwarp();

    // ---- t = 0 init (from ring slot 0) ----
    float  pt = 0.f;
    double c2;
    int    ytprev, ytcur;
    bool   pm;
    float  s0p, s1p;
    {
        float2 v = *(const float2*)(sh_em[w] + 2 * lane);
        bool okl = (v.x > -1e6f) & (v.y > -1e6f);
        bool ok0 = __all_sync(FULLMASK, okl);
        float mv0 = ok0 ? v.x : 0.f;
        float mv1 = ok0 ? v.y : 0.f;
        float mx = warp_maxf(fmaxf(mv0, mv1));
        s0p = ex2f((mv0 - mx) * LOG2E);
        s1p = ex2f((mv1 - mx) * LOG2E);
        c2 = (double)mx * 1.4426950408889634;
        ytprev = __ldg(&ytrow[0]);
        ytcur  = __ldg(&ytrow[1]);
        if (ok0 && (ytprev >> 1) == lane) pt += (ytprev & 1) ? v.y : v.x;
        pm = ok0;
        sh_a[w][0][lane] = pack2(s0p, s1p);
    }
    __syncwarp();

    float pendinv = 1.0f;   // deferred renorm scale (applied in next epilogue)
    int   buf = 0;

    // one scan step; TT/KK compile-time; RENORM compile-time
    #define STEP(TT, KK, RENORM)                                               \
    {                                                                          \
        float2 em = *(const float2*)(ebase + (KK) * 64 + 2 * lane);            \
        int yt = ytcur;                                                        \
        ytcur = __ldg(&ytrow[((TT) + 1 > N - 1) ? (N - 1) : (TT) + 1]);        \
        float trv = __ldg(&trans[ytprev * K + yt]);                            \
        float e0 = ex2f(em.x * LOG2E) * pendinv;                               \
        float e1 = ex2f(em.y * LOG2E) * pendinv;                               \
        bool ok = __all_sync(FULLMASK, (em.x > -1e6f) & (em.y > -1e6f));       \
        const ulonglong2* ap = (const ulonglong2*)sh_a[w][buf];                \
        ull A0 = 0ull, A1 = 0ull, B0 = 0ull, B1 = 0ull;                        \
        _Pragma("unroll")                                                      \
        for (int q = 0; q < 8; q++) {                                          \
            ulonglong2 v0 = ap[2 * q];                                         \
            ulonglong2 v1 = ap[2 * q + 1];                                     \
            fma2(A0, v0.x, Er0[4 * q]);                                        \
            fma2(B0, v0.x, Er1[4 * q]);                                        \
            fma2(A1, v0.y, Er0[4 * q + 1]);                                    \
            fma2(B1, v0.y, Er1[4 * q + 1]);                                    \
            fma2(A0, v1.x, Er0[4 * q + 2]);                                    \
            fma2(B0, v1.x, Er1[4 * q + 2]);                                    \
            fma2(A1, v1.y, Er0[4 * q + 3]);                                    \
            fma2(B1, v1.y, Er1[4 * q + 3]);                                    \
        }                                                                      \
        float xa, ya, xb, yb, xc, yc, xd, yd;                                  \
        unpack2(A0, xa, ya); unpack2(A1, xb, yb);                              \
        unpack2(B0, xc, yc); unpack2(B1, xd, yd);                              \
        float s0n = (((xa + xb) + (ya + yb))) * e0;                            \
        float s1n = (((xc + xd) + (yc + yd))) * e1;                            \
        float s0 = ok ? s0n : s0p;                                             \
        float s1 = ok ? s1n : s1p;                                             \
        pendinv = ok ? 1.0f : pendinv;                                         \
        bool match = ((yt >> 1) == lane) & ok;                                 \
        float femit = (yt & 1) ? em.y : em.x;                                  \
        float tadd  = pm ? trv : 0.0f;                                         \
        pt += match ? (femit + tadd) : 0.0f;                                   \
        pm = ok; ytprev = yt;                                                  \
        s0p = s0; s1p = s1;                                                    \
        sh_a[w][buf ^ 1][lane] = pack2(s0, s1);                                \
        buf ^= 1;                                                              \
        __syncwarp();                                                          \
        if (RENORM) {                                                          \
            float r = warp_maxf(fmaxf(s0, s1));                                \
            float inv = 1.0f / r;                                              \
            pendinv *= inv;                                                    \
            c2 += (double)lg2f(r);                                             \
        }                                                                      \
    }

    // ---- group 0: t = 1..7 (buffer 0 resident); renorm at t % 4 == 0 ----
    {
        PREFETCH(2)
        asm volatile("cp.async.wait_group 2;");
        __syncwarp();
        const float* ebase = sh_em[w];
        STEP(1, 1, false)
        STEP(2, 2, false)
        STEP(3, 3, false)
        STEP(4, 4, true)
        STEP(5, 5, false)
        STEP(6, 6, false)
        STEP(7, 7, false)
    }

    // ---- groups 1..127: t = 8..1023 ----
    for (int G = 1; G < 128; G++) {
        PREFETCH(G + 2)
        asm volatile("cp.async.wait_group 2;");
        __syncwarp();
        const float* ebase = sh_em[w] + (G & 3) * 512;
        const int t0 = G * 8;
        STEP(t0 + 0, 0, true)
        STEP(t0 + 1, 1, false)
        STEP(t0 + 2, 2, false)
        STEP(t0 + 3, 3, false)
        STEP(t0 + 4, 4, true)
        STEP(t0 + 5, 5, false)
        STEP(t0 + 6, 6, false)
        STEP(t0 + 7, 7, false)
    }
    #undef STEP
    #undef PREFETCH

    // ---- finalize: apply any unconsumed pending scale, reduce, output ----
    float ssum = (s0p + s1p) * pendinv;
    #pragma unroll
    for (int o = 16; o; o >>= 1) {
        ssum += __shfl_xor_sync(FULLMASK, ssum, o);
        pt   += __shfl_xor_sync(FULLMASK, pt,   o);
    }
    if (lane == 0) {
        double lognorm = (c2 + (double)lg2f(ssum)) * 0.6931471805599453;
        out[b] = (float)(lognorm - (double)pt);
    }
}

extern "C" void kernel_launch(void* const* d_in, const int* in_sizes, int n_in,
                              void* d_out, int out_size) {
    const float* y_pred = (const float*)d_in[0];
    const float* trans  = (const float*)d_in[1];
    const int*   y_true = (const int*)d_in[2];
    float* out = (float*)d_out;

    const int B = in_sizes[2] / 1024;   // 512
    crf_fwd_kernel<<<B / 4, 128>>>(y_pred, trans, y_true, out);
}

// round 13
// speedup vs baseline: 2.8846x; 1.2796x over previous
#include <cuda_runtime.h>
#include <cstdint>

// CRF loss forward, B=512, N=1024, K=64, sm_100a.
// 4 chains per 128-thread block (one warp per SMSP). Per warp: linear-domain
// scan, register-resident exp(trans), f32x2 FMAs, cp.async emit ring,
// emit/ex2/vote pipelined one step ahead, branch-free score gather,
// EXACT lane-0 power-of-2 lazy renorm every 4 steps (integer ctot).

typedef unsigned long long ull;
#define FULLMASK 0xffffffffu

__device__ __forceinline__ void fma2(ull &d, ull a, ull b) {
    asm("fma.rn.f32x2 %0, %1, %2, %0;" : "+l"(d) : "l"(a), "l"(b));
}
__device__ __forceinline__ ull pack2(float x, float y) {
    ull r; asm("mov.b64 %0, {%1, %2};" : "=l"(r) : "f"(x), "f"(y)); return r;
}
__device__ __forceinline__ void unpack2(ull v, float &x, float &y) {
    asm("mov.b64 {%0, %1}, %2;" : "=f"(x), "=f"(y) : "l"(v));
}
__device__ __forceinline__ float ex2f(float x) {
    float r; asm("ex2.approx.f32 %0, %1;" : "=f"(r) : "f"(x)); return r;
}
__device__ __forceinline__ float lg2f(float x) {
    float r; asm("lg2.approx.f32 %0, %1;" : "=f"(r) : "f"(x)); return r;
}
__device__ __forceinline__ float warp_maxf(float x) {
    #pragma unroll
    for (int o = 16; o; o >>= 1) x = fmaxf(x, __shfl_xor_sync(FULLMASK, x, o));
    return x;
}
__device__ __forceinline__ uint32_t s2u(const void* p) {
    uint32_t a;
    asm("{ .reg .u64 t; cvta.to.shared.u64 t, %1; cvt.u32.u64 %0, t; }"
        : "=r"(a) : "l"(p));
    return a;
}
__device__ __forceinline__ void cp16(uint32_t dst, const void* src) {
    asm volatile("cp.async.cg.shared.global [%0], [%1], 16;"
                 :: "r"(dst), "l"(src));
}
#define CP_COMMIT() asm volatile("cp.async.commit_group;")

__global__ __launch_bounds__(128) void crf_fwd_kernel(
    const float* __restrict__ y_pred,   // [B, N, K]
    const float* __restrict__ trans,    // [K, K]
    const int*   __restrict__ y_true,   // [B, N]
    float*       __restrict__ out)      // [B]
{
    constexpr int N = 1024;
    constexpr int K = 64;
    constexpr float LOG2E = 1.4426950408889634f;

    const int tid  = threadIdx.x;
    const int w    = tid >> 5;          // warp -> SMSP w
    const int lane = tid & 31;
    const int b    = blockIdx.x * 4 + w;
    const int j0   = 2 * lane, j1 = j0 + 1;

    __shared__ __align__(16) float sh_em[4][4 * 512];  // per-warp 4-buf emit ring
    __shared__ ull sh_a[4][2][32];                     // per-warp double-buffered alpha

    const float* emrow_f = y_pred + (size_t)b * N * K;
    const int*   ytrow   = y_true + (size_t)b * N;
    const uint32_t em_u32 = s2u(sh_em[w]);

    // issue one 8-step (2KB) emit group into ring buffer (GP&3)
    #define PREFETCH(GP)                                                       \
    {                                                                          \
        int bt = (GP) * 8; if (bt > N - 8) bt = N - 8;                         \
        const char* src = (const char*)(emrow_f + (size_t)bt * K) + lane * 16; \
        uint32_t dst = em_u32 + (uint32_t)(((GP) & 3) * 2048) + lane * 16;     \
        cp16(dst,        src);                                                 \
        cp16(dst +  512, src +  512);                                          \
        cp16(dst + 1024, src + 1024);                                          \
        cp16(dst + 1536, src + 1536);                                          \
        CP_COMMIT();                                                           \
    }

    PREFETCH(0)
    PREFETCH(1)

    // ---- E = exp(trans) columns j0, j1 in registers (overlaps cp.async) ----
    ull Er0[32], Er1[32];
    #pragma unroll
    for (int p = 0; p < 32; p++) {
        float t00 = __ldg(&trans[(2 * p)     * K + j0]);
        float t01 = __ldg(&trans[(2 * p + 1) * K + j0]);
        float t10 = __ldg(&trans[(2 * p)     * K + j1]);
        float t11 = __ldg(&trans[(2 * p + 1) * K + j1]);
        Er0[p] = pack2(ex2f(t00 * LOG2E), ex2f(t01 * LOG2E));
        Er1[p] = pack2(ex2f(t10 * LOG2E), ex2f(t11 * LOG2E));
    }

    asm volatile("cp.async.wait_group 1;");   // group 0 resident
    __syncwarp();

    // ---- t = 0 init (from ring slot 0) ----
    float  pt = 0.f;
    float  mx0;
    int    ctot = 0;     // exact power-of-2 scale accumulator (log2 units)
    int    ytprev, ytcur;
    bool   pm;
    float  s0p, s1p;
    {
        float2 v = *(const float2*)(sh_em[w] + 2 * lane);
        bool okl = (v.x > -1e6f) & (v.y > -1e6f);
        bool ok0 = __all_sync(FULLMASK, okl);
        float mv0 = ok0 ? v.x : 0.f;
        float mv1 = ok0 ? v.y : 0.f;
        float mx = warp_maxf(fmaxf(mv0, mv1));
        s0p = ex2f((mv0 - mx) * LOG2E);
        s1p = ex2f((mv1 - mx) * LOG2E);
        mx0 = mx;
        ytprev = __ldg(&ytrow[0]);
        ytcur  = __ldg(&ytrow[1]);
        if (ok0 && (ytprev >> 1) == lane) pt += (ytprev & 1) ? v.y : v.x;
        pm = ok0;
        sh_a[w][0][lane] = pack2(s0p, s1p);
    }
    __syncwarp();

    // ---- prime the one-step-ahead emit pipeline for t = 1 (slot 1) ----
    float2 em_c = *(const float2*)(sh_em[w] + 64 + 2 * lane);
    float  e0c  = ex2f(em_c.x * LOG2E);
    float  e1c  = ex2f(em_c.y * LOG2E);
    bool   okc  = __all_sync(FULLMASK, (em_c.x > -1e6f) & (em_c.y > -1e6f));

    float pendinv = 1.0f;   // exact pow-2 deferred scale
    int   buf = 0;

    // one scan step; TT/KK compile-time; RENORM compile-time.
    // uses pipelined em_c/e0c/e1c/okc, prefetches slot KK+1 for next step.
    #define STEP(TT, KK, RENORM)                                               \
    {                                                                          \
        const float* nb = ((KK) == 7) ? ebase_next : ebase;                    \
        float2 em_n = *(const float2*)(nb + (((KK) + 1) & 7) * 64 + 2 * lane); \
        float e0n = ex2f(em_n.x * LOG2E);                                      \
        float e1n = ex2f(em_n.y * LOG2E);                                      \
        bool  okn = __all_sync(FULLMASK, (em_n.x > -1e6f) & (em_n.y > -1e6f)); \
        int yt = ytcur;                                                        \
        ytcur = __ldg(&ytrow[((TT) + 1 > N - 1) ? (N - 1) : (TT) + 1]);        \
        float trv = __ldg(&trans[ytprev * K + yt]);                            \
        float e0 = e0c * pendinv;                                              \
        float e1 = e1c * pendinv;                                              \
        const ulonglong2* ap = (const ulonglong2*)sh_a[w][buf];                \
        ull A0 = 0ull, A1 = 0ull, B0 = 0ull, B1 = 0ull;                        \
        _Pragma("unroll")                                                      \
        for (int q = 0; q < 8; q++) {                                          \
            ulonglong2 v0 = ap[2 * q];                                         \
            ulonglong2 v1 = ap[2 * q + 1];                                     \
            fma2(A0, v0.x, Er0[4 * q]);                                        \
            fma2(B0, v0.x, Er1[4 * q]);                                        \
            fma2(A1, v0.y, Er0[4 * q + 1]);                                    \
            fma2(B1, v0.y, Er1[4 * q + 1]);                                    \
            fma2(A0, v1.x, Er0[4 * q + 2]);                                    \
            fma2(B0, v1.x, Er1[4 * q + 2]);                                    \
            fma2(A1, v1.y, Er0[4 * q + 3]);                                    \
            fma2(B1, v1.y, Er1[4 * q + 3]);                                    \
        }                                                                      \
        float xa, ya, xb, yb, xc, yc, xd, yd;                                  \
        unpack2(A0, xa, ya); unpack2(A1, xb, yb);                              \
        unpack2(B0, xc, yc); unpack2(B1, xd, yd);                              \
        float s0n = (((xa + xb) + (ya + yb))) * e0;                            \
        float s1n = (((xc + xd) + (yc + yd))) * e1;                            \
        float s0 = okc ? s0n : s0p;                                            \
        float s1 = okc ? s1n : s1p;                                            \
        pendinv = okc ? 1.0f : pendinv;                                        \
        bool match = ((yt >> 1) == lane) & okc;                                \
        float femit = (yt & 1) ? em_c.y : em_c.x;                              \
        float tadd  = pm ? trv : 0.0f;                                         \
        pt += match ? (femit + tadd) : 0.0f;                                   \
        pm = okc; ytprev = yt;                                                 \
        s0p = s0; s1p = s1;                                                    \
        sh_a[w][buf ^ 1][lane] = pack2(s0, s1);                                \
        buf ^= 1;                                                              \
        em_c = em_n; e0c = e0n; e1c = e1n; okc = okn;                          \
        __syncwarp();                                                          \
        if (RENORM) {                                                          \
            float r = __shfl_sync(FULLMASK, s0, 0);                            \
            int be = (__float_as_int(r) >> 23) & 0xff;                         \
            be = (be < 1) ? 127 : ((be > 253) ? 253 : be);                     \
            pendinv *= __int_as_float((254 - be) << 23);                       \
            ctot += be - 127;                                                  \
        }                                                                      \
    }

    // ---- group 0: t = 1..7; renorm at t % 4 == 0 ----
    {
        PREFETCH(2)
        asm volatile("cp.async.wait_group 1;");
        __syncwarp();
        const float* ebase      = sh_em[w];
        const float* ebase_next = sh_em[w] + 512;
        STEP(1, 1, false)
        STEP(2, 2, false)
        STEP(3, 3, false)
        STEP(4, 4, true)
        STEP(5, 5, false)
        STEP(6, 6, false)
        STEP(7, 7, false)
    }

    // ---- groups 1..127: t = 8..1023 ----
    for (int G = 1; G < 128; G++) {
        PREFETCH(G + 2)
        asm volatile("cp.async.wait_group 1;");
        __syncwarp();
        const float* ebase      = sh_em[w] + (G & 3) * 512;
        const float* ebase_next = sh_em[w] + ((G + 1) & 3) * 512;
        const int t0 = G * 8;
        STEP(t0 + 0, 0, true)
        STEP(t0 + 1, 1, false)
        STEP(t0 + 2, 2, false)
        STEP(t0 + 3, 3, false)
        STEP(t0 + 4, 4, true)
        STEP(t0 + 5, 5, false)
        STEP(t0 + 6, 6, false)
        STEP(t0 + 7, 7, false)
    }
    #undef STEP
    #undef PREFETCH

    // ---- finalize: apply unconsumed pending scale, reduce, output ----
    float ssum = (s0p + s1p) * pendinv;
    #pragma unroll
    for (int o = 16; o; o >>= 1) {
        ssum += __shfl_xor_sync(FULLMASK, ssum, o);
        pt   += __shfl_xor_sync(FULLMASK, pt,   o);
    }
    if (lane == 0) {
        double log2norm = (double)mx0 * 1.4426950408889634
                        + (double)ctot + (double)lg2f(ssum);
        out[b] = (float)(log2norm * 0.6931471805599453 - (double)pt);
    }
}

extern "C" void kernel_launch(void* const* d_in, const int* in_sizes, int n_in,
                              void* d_out, int out_size) {
    const float* y_pred = (const float*)d_in[0];
    const float* trans  = (const float*)d_in[1];
    const int*   y_true = (const int*)d_in[2];
    float* out = (float*)d_out;

    const int B = in_sizes[2] / 1024;   // 512
    crf_fwd_kernel<<<B / 4, 128>>>(y_pred, trans, y_true, out);
}